// round 1
// baseline (speedup 1.0000x reference)
#include <cuda_runtime.h>
#include <math.h>

#define T_DIM 1024
#define H_DIM 256
#define NTHREADS 256
#define NWARPS 8

__global__ __launch_bounds__(NTHREADS, 1)
void temporal_attn_causal_kernel(const float* __restrict__ h,
                                 const float* __restrict__ attn_w,
                                 const float* __restrict__ attn_b,
                                 float* __restrict__ out) {
    __shared__ float sE[T_DIM];   // scores, then e[t] = exp(s - max)
    __shared__ float sR[T_DIM];   // 1 / (cumsum(e)[t] + 1e-12)
    __shared__ float red[NWARPS]; // reduction scratch

    const int bl = blockIdx.x; // one CTA per (b, l) pair: 128 total
    const float* __restrict__ hb = h + (size_t)bl * T_DIM * H_DIM;
    float* __restrict__ ob = out + (size_t)bl * T_DIM * H_DIM;

    const int tid  = threadIdx.x;
    const int lane = tid & 31;
    const int warp = tid >> 5;

    // ---- Phase 1: scores s[t] = dot(h[t,:], w) (+ bias) ----
    // Each lane holds 8 weight values as two float4 (covers H=256 per warp).
    const float4* __restrict__ w4 = (const float4*)attn_w;
    const float4 wv0 = w4[lane];
    const float4 wv1 = w4[lane + 32];
    const float bias = attn_b[0];

    const float4* __restrict__ h4 = (const float4*)hb;
    #pragma unroll 4
    for (int t = warp; t < T_DIM; t += NWARPS) {
        const float4* row = h4 + (size_t)t * (H_DIM / 4);
        float4 a = row[lane];
        float4 c = row[lane + 32];
        float d = a.x * wv0.x + a.y * wv0.y + a.z * wv0.z + a.w * wv0.w
                + c.x * wv1.x + c.y * wv1.y + c.z * wv1.z + c.w * wv1.w;
        d += __shfl_xor_sync(0xffffffffu, d, 16);
        d += __shfl_xor_sync(0xffffffffu, d, 8);
        d += __shfl_xor_sync(0xffffffffu, d, 4);
        d += __shfl_xor_sync(0xffffffffu, d, 2);
        d += __shfl_xor_sync(0xffffffffu, d, 1);
        if (lane == 0) sE[t] = d + bias;
    }
    __syncthreads();

    // ---- Phase 2a: global max over T ----
    float m = -INFINITY;
    #pragma unroll
    for (int i = tid; i < T_DIM; i += NTHREADS) m = fmaxf(m, sE[i]);
    #pragma unroll
    for (int o = 16; o > 0; o >>= 1) m = fmaxf(m, __shfl_xor_sync(0xffffffffu, m, o));
    if (lane == 0) red[warp] = m;
    __syncthreads();
    float gmax = red[0];
    #pragma unroll
    for (int i = 1; i < NWARPS; i++) gmax = fmaxf(gmax, red[i]);
    __syncthreads(); // red reused below

    // ---- Phase 2b: e[t] = exp(s - gmax); inclusive scan -> r[t] ----
    {
        const int base = tid * 4;
        float e0 = expf(sE[base + 0] - gmax);
        float e1 = expf(sE[base + 1] - gmax);
        float e2 = expf(sE[base + 2] - gmax);
        float e3 = expf(sE[base + 3] - gmax);
        float l0 = e0;
        float l1 = l0 + e1;
        float l2 = l1 + e2;
        float l3 = l2 + e3;
        float tot = l3;

        // warp inclusive scan of per-thread totals
        float v = tot;
        #pragma unroll
        for (int o = 1; o < 32; o <<= 1) {
            float n = __shfl_up_sync(0xffffffffu, v, o);
            if (lane >= o) v += n;
        }
        if (lane == 31) red[warp] = v; // warp total
        __syncthreads();
        float warpOff = 0.f;
        for (int i = 0; i < warp; i++) warpOff += red[i];
        const float excl = warpOff + (v - tot);

        const float eps = 1e-12f;
        sE[base + 0] = e0;
        sE[base + 1] = e1;
        sE[base + 2] = e2;
        sE[base + 3] = e3;
        sR[base + 0] = 1.0f / (excl + l0 + eps);
        sR[base + 1] = 1.0f / (excl + l1 + eps);
        sR[base + 2] = 1.0f / (excl + l2 + eps);
        sR[base + 3] = 1.0f / (excl + l3 + eps);
    }
    __syncthreads();

    // ---- Phase 3: running weighted cumsum along T, thread owns h-dim j ----
    const int j = tid;
    float acc = 0.f;
    #pragma unroll 1
    for (int t0 = 0; t0 < T_DIM; t0 += 8) {
        float hv[8];
        #pragma unroll
        for (int k = 0; k < 8; k++)
            hv[k] = hb[(size_t)(t0 + k) * H_DIM + j]; // 8 independent coalesced LDGs
        float ov[8];
        #pragma unroll
        for (int k = 0; k < 8; k++) {
            const float e = sE[t0 + k];   // warp-broadcast smem load
            const float r = sR[t0 + k];
            acc = fmaf(e, hv[k], acc);
            ov[k] = fmaf(acc, r, hv[k]);  // h + acc * (1/(cumE+eps))
        }
        #pragma unroll
        for (int k = 0; k < 8; k++)
            ob[(size_t)(t0 + k) * H_DIM + j] = ov[k];
    }
}

extern "C" void kernel_launch(void* const* d_in, const int* in_sizes, int n_in,
                              void* d_out, int out_size) {
    const float* h      = (const float*)d_in[0]; // [8,16,1024,256] f32
    const float* attn_w = (const float*)d_in[1]; // [256] f32
    const float* attn_b = (const float*)d_in[2]; // [1] f32
    float* out = (float*)d_out;
    (void)in_sizes; (void)n_in; (void)out_size;

    temporal_attn_causal_kernel<<<128, NTHREADS>>>(h, attn_w, attn_b, out);
}

// round 3
// speedup vs baseline: 2.8535x; 2.8535x over previous
#include <cuda_runtime.h>
#include <cstdint>
#include <math.h>

#define T_DIM   1024
#define H_DIM   256
#define NTHREADS 256
#define NWARPS  8
#define CHUNK   32                 // t-rows per tile
#define NCHUNK  (T_DIM / CHUNK)    // 32
#define PIPE    3                  // smem pipeline stages

#define TILE_FLOATS (CHUNK * H_DIM)        // 8192 floats = 32 KB
#define TILE_BYTES  (TILE_FLOATS * 4)

// dynamic smem layout:
// [0)                        buf[PIPE][CHUNK][H]          98304 B
// [+PIPE*TILE_FLOATS)        sS[CHUNK], sEv[CHUNK], sRv[CHUNK], sMisc[4]
// then (8B aligned)          mbar[PIPE]
#define SMEM_FLOATS (PIPE * TILE_FLOATS + 3 * CHUNK + 4)
#define SMEM_BYTES  (SMEM_FLOATS * 4 + PIPE * 8)

__device__ __forceinline__ uint32_t smem_u32(const void* p) {
    uint32_t a;
    asm("{ .reg .u64 t; cvta.to.shared.u64 t, %1; cvt.u32.u64 %0, t; }" : "=r"(a) : "l"(p));
    return a;
}

__device__ __forceinline__ void mbar_init(uint32_t mbar, uint32_t count) {
    asm volatile("mbarrier.init.shared.b64 [%0], %1;" :: "r"(mbar), "r"(count) : "memory");
}
__device__ __forceinline__ void mbar_expect_tx(uint32_t mbar, uint32_t bytes) {
    asm volatile("mbarrier.arrive.expect_tx.shared.b64 _, [%0], %1;" :: "r"(mbar), "r"(bytes) : "memory");
}
__device__ __forceinline__ void bulk_g2s(uint32_t dst, const void* src, uint32_t bytes, uint32_t mbar) {
    asm volatile("cp.async.bulk.shared::cta.global.mbarrier::complete_tx::bytes [%0], [%1], %2, [%3];"
                 :: "r"(dst), "l"(src), "r"(bytes), "r"(mbar) : "memory");
}
__device__ __forceinline__ void mbar_wait_parity(uint32_t mbar, uint32_t parity) {
    uint32_t done;
    asm volatile(
        "{\n\t.reg .pred p;\n\t"
        "mbarrier.try_wait.parity.acquire.cta.shared::cta.b64 p, [%1], %2;\n\t"
        "selp.b32 %0, 1, 0, p;\n\t}"
        : "=r"(done) : "r"(mbar), "r"(parity) : "memory");
    if (!done) {
        asm volatile(
            "{\n\t.reg .pred P1;\n\t"
            "WL_%=:\n\t"
            "mbarrier.try_wait.parity.acquire.cta.shared::cta.b64 P1, [%0], %1, 0x989680;\n\t"
            "@P1 bra.uni WD_%=;\n\t"
            "bra.uni WL_%=;\n\t"
            "WD_%=:\n\t}"
            :: "r"(mbar), "r"(parity) : "memory");
    }
}

__global__ __launch_bounds__(NTHREADS, 1)
void temporal_attn_causal_kernel(const float* __restrict__ h,
                                 const float* __restrict__ attn_w,
                                 const float* __restrict__ attn_b,
                                 float* __restrict__ out) {
    extern __shared__ __align__(16) unsigned char smem_raw[];
    float*    buf   = (float*)smem_raw;                      // PIPE tiles
    float*    sS    = buf + PIPE * TILE_FLOATS;              // scores [CHUNK]
    float*    sEv   = sS + CHUNK;                            // e[k]
    float*    sRv   = sEv + CHUNK;                           // 1/cumE[k]
    float*    sMisc = sRv + CHUNK;                           // [0] = rescale factor
    uint64_t* mbar  = (uint64_t*)(sMisc + 4);

    const int bl   = blockIdx.x;                 // one CTA per (b,l): 128
    const int tid  = threadIdx.x;
    const int lane = tid & 31;
    const int warp = tid >> 5;

    const float* __restrict__ hb = h + (size_t)bl * T_DIM * H_DIM;
    float* __restrict__ ob = out + (size_t)bl * T_DIM * H_DIM;

    // per-lane weight cache for score dot products (all warps)
    const float4* __restrict__ w4 = (const float4*)attn_w;
    const float4 wv0 = w4[lane];
    const float4 wv1 = w4[lane + 32];
    const float bias = attn_b[0];

    // ---- pipeline init ----
    if (tid == 0) {
        #pragma unroll
        for (int s = 0; s < PIPE; s++) mbar_init(smem_u32(&mbar[s]), 1);
        asm volatile("fence.proxy.async.shared::cta;" ::: "memory");
    }
    __syncthreads();

    if (tid == 0) {
        #pragma unroll
        for (int s = 0; s < PIPE; s++) {
            uint32_t mb = smem_u32(&mbar[s]);
            mbar_expect_tx(mb, TILE_BYTES);
            bulk_g2s(smem_u32(buf + s * TILE_FLOATS),
                     hb + (size_t)s * TILE_FLOATS, TILE_BYTES, mb);
        }
    }

    // ---- online running-max softmax state (warp 0 lanes + per-thread acc) ----
    float m_run = -INFINITY;   // valid in warp 0
    float carry = 0.f;         // cumE carry, valid in warp 0
    float acc   = 0.f;         // per-thread: running sum e*h for dim j=tid

    for (int g = 0; g < NCHUNK; g++) {
        const int   stage = g % PIPE;
        const uint32_t parity = (uint32_t)((g / PIPE) & 1);
        float* tile = buf + stage * TILE_FLOATS;

        mbar_wait_parity(smem_u32(&mbar[stage]), parity);

        // ---- scores: warp per t-row, float4 smem reads + shuffle reduce ----
        #pragma unroll
        for (int i = 0; i < CHUNK / NWARPS; i++) {
            const int t = warp + i * NWARPS;
            const float4* row = (const float4*)(tile + t * H_DIM);
            float4 a = row[lane];
            float4 c = row[lane + 32];
            float d = a.x * wv0.x + a.y * wv0.y + a.z * wv0.z + a.w * wv0.w
                    + c.x * wv1.x + c.y * wv1.y + c.z * wv1.z + c.w * wv1.w;
            d += __shfl_xor_sync(0xffffffffu, d, 16);
            d += __shfl_xor_sync(0xffffffffu, d, 8);
            d += __shfl_xor_sync(0xffffffffu, d, 4);
            d += __shfl_xor_sync(0xffffffffu, d, 2);
            d += __shfl_xor_sync(0xffffffffu, d, 1);
            if (lane == 0) sS[t] = d + bias;
        }
        __syncthreads();

        // ---- warp 0: running max update + exp + inclusive scan of e ----
        if (warp == 0) {
            float s_k = sS[lane];
            // chunk max
            float gm = s_k;
            #pragma unroll
            for (int o = 16; o > 0; o >>= 1)
                gm = fmaxf(gm, __shfl_xor_sync(0xffffffffu, gm, o));
            float scale = 1.0f;
            if (gm > m_run) {
                scale = __expf(m_run - gm);   // 0 on first chunk (m_run = -inf)
                m_run = gm;
            }
            float e = __expf(s_k - m_run);
            // inclusive scan over 32 lanes
            float c = e;
            #pragma unroll
            for (int o = 1; o < 32; o <<= 1) {
                float n = __shfl_up_sync(0xffffffffu, c, o);
                if (lane >= o) c += n;
            }
            carry *= scale;
            float tot = carry + c;
            float r = 1.0f / (tot + 1e-12f * __expf(-m_run));
            sEv[lane] = e;
            sRv[lane] = r;
            carry = __shfl_sync(0xffffffffu, tot, 31);
            if (lane == 0) sMisc[0] = scale;
        }
        __syncthreads();

        // ---- emit: thread owns dim j = tid, sequential over CHUNK t's ----
        acc *= sMisc[0];
        float* outg = ob + (size_t)g * TILE_FLOATS + tid;
        #pragma unroll
        for (int k = 0; k < CHUNK; k++) {
            float hv = tile[k * H_DIM + tid];
            acc = fmaf(sEv[k], hv, acc);
            __stcs(outg + k * H_DIM, fmaf(acc, sRv[k], hv));
        }
        __syncthreads();  // tile fully consumed before refill

        if (tid == 0 && g + PIPE < NCHUNK) {
            uint32_t mb = smem_u32(&mbar[stage]);
            mbar_expect_tx(mb, TILE_BYTES);
            bulk_g2s(smem_u32(tile), hb + (size_t)(g + PIPE) * TILE_FLOATS,
                     TILE_BYTES, mb);
        }
    }
}

extern "C" void kernel_launch(void* const* d_in, const int* in_sizes, int n_in,
                              void* d_out, int out_size) {
    const float* h      = (const float*)d_in[0]; // [8,16,1024,256] f32
    const float* attn_w = (const float*)d_in[1]; // [256] f32
    const float* attn_b = (const float*)d_in[2]; // [1] f32
    float* out = (float*)d_out;
    (void)in_sizes; (void)n_in; (void)out_size;

    static bool attr_set = false;
    if (!attr_set) {
        cudaFuncSetAttribute(temporal_attn_causal_kernel,
                             cudaFuncAttributeMaxDynamicSharedMemorySize, SMEM_BYTES);
        attr_set = true;
    }
    temporal_attn_causal_kernel<<<128, NTHREADS, SMEM_BYTES>>>(h, attn_w, attn_b, out);
}